// round 1
// baseline (speedup 1.0000x reference)
#include <cuda_runtime.h>
#include <math.h>

#define N_QUBITS 8
#define HW 65536           // 256*256
#define CC 64              // channels
#define OO 64              // output channels
#define BB 16              // batch
#define PIF 3.14159265358979323846f

// ---------------- device scratch (no allocations allowed) ----------------
__device__ float g_xglobal[BB * CC];   // per (b,c) spatial mean
__device__ float g_add[BB * OO];       // conv_b[o] + gate_b * g_b[o]

// ---------------- f32x2 helpers (packed dual-FMA, full-rate on B300) -----
__device__ __forceinline__ void ffma2(unsigned long long& d,
                                      unsigned long long a,
                                      unsigned long long b) {
    asm("fma.rn.f32x2 %0, %1, %2, %0;" : "+l"(d) : "l"(a), "l"(b));
}
__device__ __forceinline__ unsigned long long pack2(float x, float y) {
    unsigned long long r;
    asm("mov.b64 %0, {%1, %2};" : "=l"(r) : "f"(x), "f"(y));
    return r;
}
__device__ __forceinline__ float2 unpack2(unsigned long long v) {
    float2 f;
    asm("mov.b64 {%0, %1}, %2;" : "=f"(f.x), "=f"(f.y) : "l"(v));
    return f;
}

// ================= K1: per-(b,c) spatial mean =============================
// grid = 1024 blocks (one per (b,c)), 256 threads, float4 streaming loads.
__global__ void k_reduce(const float* __restrict__ x) {
    const float4* p = reinterpret_cast<const float4*>(x + (size_t)blockIdx.x * HW);
    float s = 0.0f;
    #pragma unroll 8
    for (int i = threadIdx.x; i < HW / 4; i += 256) {
        float4 v = p[i];
        s += (v.x + v.y) + (v.z + v.w);
    }
    #pragma unroll
    for (int o = 16; o; o >>= 1) s += __shfl_xor_sync(0xffffffffu, s, o);
    __shared__ float ws[8];
    if ((threadIdx.x & 31) == 0) ws[threadIdx.x >> 5] = s;
    __syncthreads();
    if (threadIdx.x == 0) {
        float t = 0.0f;
        #pragma unroll
        for (int w = 0; w < 8; w++) t += ws[w];
        g_xglobal[blockIdx.x] = t * (1.0f / (float)HW);
    }
}

// ================= K2: quantum circuit + gate + MLP =======================
// 1 block, 512 threads = 16 warps; warp b handles batch b.
__global__ void k_small(const float* __restrict__ cw,     // channel_weights [64]
                        const float* __restrict__ qw,     // quantum_weights [24]
                        const float* __restrict__ w1,     // [64,8]
                        const float* __restrict__ b1,     // [64]
                        const float* __restrict__ w2,     // [64,64]
                        const float* __restrict__ b2,     // [64]
                        const float* __restrict__ conv_b, // [64]
                        float* __restrict__ out,          // d_out base
                        int out_size) {
    __shared__ float sh_h[BB][OO];
    int b = threadIdx.x >> 5;
    int lane = threadIdx.x & 31;

    // --- quantum expvals: 4 independent 2-qubit real states (redundant per lane)
    float xq[N_QUBITS];
    #pragma unroll
    for (int p = 0; p < 4; p++) {
        int ia = 2 * p, ib = 2 * p + 1;
        float in_a = g_xglobal[b * CC + ia] * cw[ia];
        float in_b = g_xglobal[b * CC + ib] * cw[ib];
        float ta = PIF * in_a + qw[ia];
        float tb = PIF * in_b + qw[ib];
        float sa, ca, sb, cb;
        sincosf(ta * 0.5f, &sa, &ca);
        sincosf(tb * 0.5f, &sb, &cb);
        float psi00 = ca * cb, psi01 = ca * sb, psi10 = sa * sb, psi11 = sa * cb;
        float shA, chA, shB, chB;
        sincosf(qw[8 + ia] * 0.5f, &shA, &chA);
        sincosf(qw[8 + ib] * 0.5f, &shB, &chB);
        // M = Ra * psi
        float m00 = chA * psi00 - shA * psi10, m01 = chA * psi01 - shA * psi11;
        float m10 = shA * psi00 + chA * psi10, m11 = shA * psi01 + chA * psi11;
        // psi' = M * Rb^T
        float q00 = m00 * chB - m01 * shB, q01 = m00 * shB + m01 * chB;
        float q10 = m10 * chB - m11 * shB, q11 = m10 * shB + m11 * chB;
        float p00 = q00 * q00, p01 = q01 * q01, p10 = q10 * q10, p11 = q11 * q11;
        xq[ia] = (p00 + p01) - (p10 + p11);  // <Z_a>
        xq[ib] = (p00 + p10) - (p01 + p11);  // <Z_b>
    }
    float ss = 0.0f;
    #pragma unroll
    for (int i = 0; i < N_QUBITS; i++) ss += xq[i] * xq[i];
    float strength = sqrtf(ss);
    float gate = 1.0f / (1.0f + expf(-(strength - 0.05f)));

    // --- h = relu(xq @ w1^T + b1) : lanes split the 64 hidden units
    #pragma unroll
    for (int rep = 0; rep < 2; rep++) {
        int j = lane + rep * 32;
        float hv = b1[j];
        #pragma unroll
        for (int i = 0; i < N_QUBITS; i++) hv += xq[i] * w1[j * N_QUBITS + i];
        sh_h[b][j] = fmaxf(hv, 0.0f);
    }
    __syncwarp();

    // --- g = h @ w2^T + b2 ; fold gate + conv_b into per-(b,o) add term
    #pragma unroll
    for (int rep = 0; rep < 2; rep++) {
        int o = lane + rep * 32;
        float gv = b2[o];
        #pragma unroll 8
        for (int j = 0; j < OO; j++) gv += sh_h[b][j] * w2[o * OO + j];
        g_add[b * OO + o] = conv_b[o] + gate * gv;
    }

    // --- auxiliary outputs (tuple concat layout), guarded by out_size
    const long long base = (long long)BB * OO * HW;
    if (out_size >= (int)0 && (long long)out_size >= base + BB * N_QUBITS + BB) {
        if (lane < N_QUBITS) out[base + b * N_QUBITS + lane] = xq[lane];
        if (lane == 0) out[base + BB * N_QUBITS + b] = strength;
    }
}

// ================= K3: 64x64 1x1-conv GEMM with packed f32x2 ==============
// grid = (HW/256, B). 256 threads: 4 o-groups (16 outs each) x 64 pixel-groups
// (4 px each). Weights duplicated (w,w) in SMEM so each LDS.128 feeds 2 FFMA2.
__global__ void __launch_bounds__(256, 2)
k_conv(const float* __restrict__ x, const float* __restrict__ conv_w,
       float* __restrict__ out) {
    __shared__ __align__(16) unsigned long long wdup[CC * OO];  // [c][o] = (w,w), 32KB

    int tid = threadIdx.x;
    #pragma unroll
    for (int e = tid; e < CC * OO; e += 256) {
        int c = e >> 6, o = e & 63;
        float w = conv_w[o * CC + c];
        wdup[c * OO + o] = pack2(w, w);
    }
    __syncthreads();

    const int og = tid >> 6;   // 0..3  -> outputs og*16 .. og*16+15
    const int pg = tid & 63;   // 0..63 -> pixels  pg*4 .. pg*4+3 within tile
    const int b = blockIdx.y;
    const int px0 = blockIdx.x * 256 + pg * 4;

    const ulonglong2* xp = reinterpret_cast<const ulonglong2*>(
        x + (size_t)b * CC * HW + px0);                 // c-stride = HW/4 ull2
    const ulonglong2* wsh = reinterpret_cast<const ulonglong2*>(wdup) + og * 8;

    unsigned long long acc[32];
    #pragma unroll
    for (int i = 0; i < 32; i++) acc[i] = 0ull;

    ulonglong2 xv = xp[0];
    #pragma unroll 4
    for (int c = 0; c < CC; c++) {
        ulonglong2 xn;
        if (c + 1 < CC) xn = xp[(size_t)(c + 1) * (HW / 4)];
        const ulonglong2* wr = wsh + (size_t)c * (OO / 2);
        #pragma unroll
        for (int i = 0; i < 8; i++) {
            ulonglong2 wv = wr[i];                      // outputs 2i, 2i+1 (dup-packed)
            ffma2(acc[4 * i + 0], wv.x, xv.x);
            ffma2(acc[4 * i + 1], wv.x, xv.y);
            ffma2(acc[4 * i + 2], wv.y, xv.x);
            ffma2(acc[4 * i + 3], wv.y, xv.y);
        }
        xv = xn;
    }

    float* ob = out + ((size_t)b * OO + og * 16) * HW + px0;
    const float* ap = g_add + b * OO + og * 16;
    #pragma unroll
    for (int j = 0; j < 16; j++) {
        float a = ap[j];
        int base = 4 * (j >> 1) + (j & 1) * 2;
        float2 p0 = unpack2(acc[base]);
        float2 p1 = unpack2(acc[base + 1]);
        float4 r = make_float4(p0.x + a, p0.y + a, p1.x + a, p1.y + a);
        *reinterpret_cast<float4*>(ob + (size_t)j * HW) = r;
    }
}

// ================= launch =================================================
extern "C" void kernel_launch(void* const* d_in, const int* in_sizes, int n_in,
                              void* d_out, int out_size) {
    const float* x       = (const float*)d_in[0];
    const float* cw      = (const float*)d_in[1];
    const float* qw      = (const float*)d_in[2];
    const float* w1      = (const float*)d_in[3];
    const float* b1      = (const float*)d_in[4];
    const float* w2      = (const float*)d_in[5];
    const float* b2      = (const float*)d_in[6];
    const float* conv_w  = (const float*)d_in[7];
    const float* conv_b  = (const float*)d_in[8];
    float* out = (float*)d_out;

    k_reduce<<<BB * CC, 256>>>(x);
    k_small<<<1, BB * 32>>>(cw, qw, w1, b1, w2, b2, conv_b, out, out_size);
    k_conv<<<dim3(HW / 256, BB), 256>>>(x, conv_w, out);
}

// round 2
// speedup vs baseline: 1.1237x; 1.1237x over previous
#include <cuda_runtime.h>
#include <math.h>
#include <stdint.h>

#define N_QUBITS 8
#define HW 65536           // 256*256
#define CC 64              // channels
#define OO 64              // output channels
#define BB 16              // batch
#define PIF 3.14159265358979323846f

// ---------------- device scratch (no allocations allowed) ----------------
__device__ float g_xglobal[BB * CC];   // per (b,c) spatial mean
__device__ float g_add[BB * OO];       // conv_b[o] + gate_b * g_b[o]

// ---------------- f32x2 helpers (packed dual-FMA) ------------------------
__device__ __forceinline__ void ffma2(unsigned long long& d,
                                      unsigned long long a,
                                      unsigned long long b) {
    asm("fma.rn.f32x2 %0, %1, %2, %0;" : "+l"(d) : "l"(a), "l"(b));
}
__device__ __forceinline__ unsigned long long pack2(float x, float y) {
    unsigned long long r;
    asm("mov.b64 %0, {%1, %2};" : "=l"(r) : "f"(x), "f"(y));
    return r;
}
__device__ __forceinline__ float2 unpack2(unsigned long long v) {
    float2 f;
    asm("mov.b64 {%0, %1}, %2;" : "=f"(f.x), "=f"(f.y) : "l"(v));
    return f;
}

// ---------------- cp.async helpers ---------------------------------------
__device__ __forceinline__ void cp_async16(uint32_t s, const float* g) {
    asm volatile("cp.async.cg.shared.global [%0], [%1], 16;\n"
                 :: "r"(s), "l"(__cvta_generic_to_global(g)));
}
__device__ __forceinline__ void cp_commit() {
    asm volatile("cp.async.commit_group;\n");
}
template <int N>
__device__ __forceinline__ void cp_wait() {
    asm volatile("cp.async.wait_group %0;\n" :: "n"(N));
}

// ================= K1: per-(b,c) spatial mean =============================
__global__ void k_reduce(const float* __restrict__ x) {
    const float4* p = reinterpret_cast<const float4*>(x + (size_t)blockIdx.x * HW);
    float s = 0.0f;
    #pragma unroll 8
    for (int i = threadIdx.x; i < HW / 4; i += 256) {
        float4 v = p[i];
        s += (v.x + v.y) + (v.z + v.w);
    }
    #pragma unroll
    for (int o = 16; o; o >>= 1) s += __shfl_xor_sync(0xffffffffu, s, o);
    __shared__ float ws[8];
    if ((threadIdx.x & 31) == 0) ws[threadIdx.x >> 5] = s;
    __syncthreads();
    if (threadIdx.x == 0) {
        float t = 0.0f;
        #pragma unroll
        for (int w = 0; w < 8; w++) t += ws[w];
        g_xglobal[blockIdx.x] = t * (1.0f / (float)HW);
    }
}

// ================= K2: quantum circuit + gate + MLP =======================
__global__ void k_small(const float* __restrict__ cw,
                        const float* __restrict__ qw,
                        const float* __restrict__ w1,
                        const float* __restrict__ b1,
                        const float* __restrict__ w2,
                        const float* __restrict__ b2,
                        const float* __restrict__ conv_b,
                        float* __restrict__ out,
                        int out_size) {
    __shared__ float sh_h[BB][OO];
    int b = threadIdx.x >> 5;
    int lane = threadIdx.x & 31;

    float xq[N_QUBITS];
    #pragma unroll
    for (int p = 0; p < 4; p++) {
        int ia = 2 * p, ib = 2 * p + 1;
        float in_a = g_xglobal[b * CC + ia] * cw[ia];
        float in_b = g_xglobal[b * CC + ib] * cw[ib];
        float ta = PIF * in_a + qw[ia];
        float tb = PIF * in_b + qw[ib];
        float sa, ca, sb, cb;
        sincosf(ta * 0.5f, &sa, &ca);
        sincosf(tb * 0.5f, &sb, &cb);
        float psi00 = ca * cb, psi01 = ca * sb, psi10 = sa * sb, psi11 = sa * cb;
        float shA, chA, shB, chB;
        sincosf(qw[8 + ia] * 0.5f, &shA, &chA);
        sincosf(qw[8 + ib] * 0.5f, &shB, &chB);
        float m00 = chA * psi00 - shA * psi10, m01 = chA * psi01 - shA * psi11;
        float m10 = shA * psi00 + chA * psi10, m11 = shA * psi01 + chA * psi11;
        float q00 = m00 * chB - m01 * shB, q01 = m00 * shB + m01 * chB;
        float q10 = m10 * chB - m11 * shB, q11 = m10 * shB + m11 * chB;
        float p00 = q00 * q00, p01 = q01 * q01, p10 = q10 * q10, p11 = q11 * q11;
        xq[ia] = (p00 + p01) - (p10 + p11);
        xq[ib] = (p00 + p10) - (p01 + p11);
    }
    float ss = 0.0f;
    #pragma unroll
    for (int i = 0; i < N_QUBITS; i++) ss += xq[i] * xq[i];
    float strength = sqrtf(ss);
    float gate = 1.0f / (1.0f + expf(-(strength - 0.05f)));

    #pragma unroll
    for (int rep = 0; rep < 2; rep++) {
        int j = lane + rep * 32;
        float hv = b1[j];
        #pragma unroll
        for (int i = 0; i < N_QUBITS; i++) hv += xq[i] * w1[j * N_QUBITS + i];
        sh_h[b][j] = fmaxf(hv, 0.0f);
    }
    __syncwarp();

    #pragma unroll
    for (int rep = 0; rep < 2; rep++) {
        int o = lane + rep * 32;
        float gv = b2[o];
        #pragma unroll 8
        for (int j = 0; j < OO; j++) gv += sh_h[b][j] * w2[o * OO + j];
        g_add[b * OO + o] = conv_b[o] + gate * gv;
    }

    const long long base = (long long)BB * OO * HW;
    if ((long long)out_size >= base + BB * N_QUBITS + BB) {
        if (lane < N_QUBITS) out[base + b * N_QUBITS + lane] = xq[lane];
        if (lane == 0) out[base + BB * N_QUBITS + b] = strength;
    }
}

// ================= K3: 64x64 1x1-conv GEMM ================================
// SMEM-staged, cp.async double-buffered, packed f32x2 math.
// grid = (HW/256, B), 256 threads: 4 o-groups (16 o) x 64 px-groups (4 px).
// SMEM: weights dup-packed (32 KB) + x stages 2 x 8c x 256px (16 KB) = 48 KB.
#define CHUNK 8                       // channels per stage
#define NCHUNK (CC / CHUNK)           // 8

__global__ void __launch_bounds__(256, 2)
k_conv(const float* __restrict__ x, const float* __restrict__ conv_w,
       float* __restrict__ out) {
    __shared__ __align__(16) unsigned long long smem_w[CC * OO];     // 32 KB
    __shared__ __align__(16) float smem_x[2][CHUNK][256];            // 16 KB

    const int tid = threadIdx.x;

    // dup-packed weights: smem_w[c*64+o] = (w,w)
    #pragma unroll
    for (int e = tid; e < CC * OO; e += 256) {
        int c = e >> 6, o = e & 63;
        float w = conv_w[o * CC + c];
        smem_w[c * OO + o] = pack2(w, w);
    }

    const int og = tid >> 6;    // 0..3  -> o = og*16 .. og*16+15
    const int pg = tid & 63;    // 0..63 -> px = pg*4 .. pg*4+3
    const int b = blockIdx.y;
    const int px0 = blockIdx.x * 256;

    const float* xb = x + (size_t)b * CC * HW + px0;

    // cp.async staging map: 512 x 16B per stage; idx -> (ci, 16B-slot)
    const int ld_ci0 = tid >> 6;           // rows 0..3   (idx = tid)
    const int ld_sl0 = tid & 63;
    const int ld_ci1 = 4 + (tid >> 6);     // rows 4..7   (idx = tid+256)
    const int ld_sl1 = tid & 63;

    uint32_t sx_base = (uint32_t)__cvta_generic_to_shared(&smem_x[0][0][0]);

    auto prefetch = [&](int chunk, int stage) {
        uint32_t sdst = sx_base + stage * (CHUNK * 256 * 4);
        const float* g0 = xb + (size_t)(chunk * CHUNK + ld_ci0) * HW + ld_sl0 * 4;
        const float* g1 = xb + (size_t)(chunk * CHUNK + ld_ci1) * HW + ld_sl1 * 4;
        cp_async16(sdst + (ld_ci0 * 256 + ld_sl0 * 4) * 4, g0);
        cp_async16(sdst + (ld_ci1 * 256 + ld_sl1 * 4) * 4, g1);
        cp_commit();
    };

    unsigned long long acc[32];
    #pragma unroll
    for (int i = 0; i < 32; i++) acc[i] = 0ull;

    prefetch(0, 0);
    __syncthreads();   // weights ready (also orders stage-0 usage vs fill loop)

    #pragma unroll 1
    for (int k = 0; k < NCHUNK; k++) {
        const int stage = k & 1;
        if (k + 1 < NCHUNK) {
            prefetch(k + 1, stage ^ 1);
            cp_wait<1>();
        } else {
            cp_wait<0>();
        }
        __syncthreads();

        const float* xrow = &smem_x[stage][0][0];
        #pragma unroll
        for (int ci = 0; ci < CHUNK; ci++) {
            ulonglong2 xv = *reinterpret_cast<const ulonglong2*>(xrow + ci * 256 + pg * 4);
            const ulonglong2* wr =
                reinterpret_cast<const ulonglong2*>(smem_w + (k * CHUNK + ci) * OO) + og * 8;
            #pragma unroll
            for (int j = 0; j < 8; j++) {
                ulonglong2 wv = wr[j];                 // o pair (2j, 2j+1), dup-packed
                ffma2(acc[4 * j + 0], wv.x, xv.x);
                ffma2(acc[4 * j + 1], wv.x, xv.y);
                ffma2(acc[4 * j + 2], wv.y, xv.x);
                ffma2(acc[4 * j + 3], wv.y, xv.y);
            }
        }
        __syncthreads();   // all reads of this stage done before it is refilled
    }

    float* ob = out + ((size_t)b * OO + og * 16) * HW + px0 + pg * 4;
    const float* ap = g_add + b * OO + og * 16;
    #pragma unroll
    for (int o2 = 0; o2 < 16; o2++) {
        float a = ap[o2];
        int j = o2 >> 1, hi = o2 & 1;
        float2 p01 = unpack2(acc[4 * j + 2 * hi + 0]);
        float2 p23 = unpack2(acc[4 * j + 2 * hi + 1]);
        float4 r = make_float4(p01.x + a, p01.y + a, p23.x + a, p23.y + a);
        *reinterpret_cast<float4*>(ob + (size_t)o2 * HW) = r;
    }
}

// ================= launch =================================================
extern "C" void kernel_launch(void* const* d_in, const int* in_sizes, int n_in,
                              void* d_out, int out_size) {
    const float* x       = (const float*)d_in[0];
    const float* cw      = (const float*)d_in[1];
    const float* qw      = (const float*)d_in[2];
    const float* w1      = (const float*)d_in[3];
    const float* b1      = (const float*)d_in[4];
    const float* w2      = (const float*)d_in[5];
    const float* b2      = (const float*)d_in[6];
    const float* conv_w  = (const float*)d_in[7];
    const float* conv_b  = (const float*)d_in[8];
    float* out = (float*)d_out;

    k_reduce<<<BB * CC, 256>>>(x);
    k_small<<<1, BB * 32>>>(cw, qw, w1, b1, w2, b2, conv_b, out, out_size);
    k_conv<<<dim3(HW / 256, BB), 256>>>(x, conv_w, out);
}